// round 8
// baseline (speedup 1.0000x reference)
#include <cuda_runtime.h>
#include <cstdint>

// out[n] = embedding[hash(trunc(x[n]*128))]  (reference's xf==0 collapses the
// trilerp to corner 0, weight 1; bit-exact).
// hash = (u0 ^ u1*2654435761 ^ u2*805459861) & (2^19 - 1)
//
// R8: beat the within-LDG replay rate. Previous pair-gather LDG.128 touched
// 16 distinct lines per instruction -> every gather wavefront pays the 2.07
// cyc within-LDG replay cost (B300-measured), which is exactly the 22.5us
// plateau. Now 8 lanes cooperatively load one 32B row with LDG.32 (one
// sector -> 1 wavefront per row, 4 rows per warp instruction), so
// independent gather LDGs pipeline at the ~1.0 cyc/wf cross-LDG rate.
// Hashes computed one-per-lane, distributed via shfl. Stores: warp writes
// 4 pts x 32B = 128B contiguous per STG.32 = 1 wf.

static constexpr unsigned P1 = 2654435761u;
static constexpr unsigned P2 = 805459861u;
static constexpr unsigned HASH_MASK = 524288u - 1u;  // 2^19
static constexpr int THREADS = 256;
static constexpr int PTS_PER_BLOCK = 512;            // 8 warps * 64 pts

__device__ __forceinline__ unsigned hash3f(float a, float b, float c)
{
    unsigned u0 = (unsigned)__float2int_rz(a * 128.0f);
    unsigned u1 = (unsigned)__float2int_rz(b * 128.0f);
    unsigned u2 = (unsigned)__float2int_rz(c * 128.0f);
    return (u0 ^ (u1 * P1) ^ (u2 * P2)) & HASH_MASK;
}

__global__ void __launch_bounds__(THREADS)
hashgrid_octet_kernel(const float* __restrict__ x,
                      const float* __restrict__ embw,   // word view of [H][8]
                      float* __restrict__ outw)         // word view of [N][8]
{
    const int tid  = threadIdx.x;
    const int w    = tid >> 5;
    const int L    = tid & 31;
    const int sub  = L >> 3;   // which of 4 rows this lane helps gather
    const int word = L & 7;    // which 4B word of the 32B row

    const size_t wb = (size_t)blockIdx.x * PTS_PER_BLOCK + (size_t)w * 64;

    // ---- hash one point per lane, two iterations (64 pts per warp) ----
    unsigned h[2];
#pragma unroll
    for (int it = 0; it < 2; it++) {
        size_t p = wb + it * 32 + L;
        float a = x[3 * p + 0];
        float b = x[3 * p + 1];
        float c = x[3 * p + 2];
        h[it] = hash3f(a, b, c);
    }

    // ---- gather: 16 independent LDG.32, 4 rows per instruction ----
    float v[16];
#pragma unroll
    for (int it = 0; it < 2; it++) {
#pragma unroll
        for (int s = 0; s < 8; s++) {
            unsigned hs = __shfl_sync(0xFFFFFFFFu, h[it], 4 * s + sub);
            v[it * 8 + s] = __ldg(&embw[(size_t)hs * 8 + word]);
        }
    }

    // ---- stores: each STG.32 writes 128B contiguous (4 pts) ----
#pragma unroll
    for (int it = 0; it < 2; it++) {
#pragma unroll
        for (int s = 0; s < 8; s++) {
            size_t p = wb + it * 32 + 4 * s + sub;
            outw[p * 8 + word] = v[it * 8 + s];
        }
    }
}

// ---------------- fallback (proven R3) for non-multiple sizes ----------------

__global__ void __launch_bounds__(THREADS)
hashgrid_gather_ilp4_kernel(const float* __restrict__ x,
                            const float4* __restrict__ emb,
                            float4* __restrict__ out,
                            int n)
{
    int tid  = threadIdx.x;
    int w    = tid >> 5;
    int lane = tid & 31;
    int qw   = lane >> 1;
    int half = lane & 1;
    int base = blockIdx.x * PTS_PER_BLOCK + w * 64 + qw;

    float xv[4][3];
#pragma unroll
    for (int k = 0; k < 4; k++) {
        int p = base + 16 * k;
        if (p < n) {
            xv[k][0] = x[3 * p + 0];
            xv[k][1] = x[3 * p + 1];
            xv[k][2] = x[3 * p + 2];
        }
    }
    unsigned h[4];
#pragma unroll
    for (int k = 0; k < 4; k++)
        h[k] = hash3f(xv[k][0], xv[k][1], xv[k][2]);

    float4 v[4];
#pragma unroll
    for (int k = 0; k < 4; k++)
        if (base + 16 * k < n) v[k] = __ldg(&emb[2 * h[k] + half]);
#pragma unroll
    for (int k = 0; k < 4; k++) {
        int p = base + 16 * k;
        if (p < n) out[2 * p + half] = v[k];
    }
}

extern "C" void kernel_launch(void* const* d_in, const int* in_sizes, int n_in,
                              void* d_out, int out_size)
{
    const float* x   = (const float*)d_in[0];
    const float* emb = (const float*)d_in[1];
    float*       out = (float*)d_out;

    int n = in_sizes[0] / 3;  // N_POINTS

    if (n % PTS_PER_BLOCK == 0) {
        int blocks = n / PTS_PER_BLOCK;  // 4096
        hashgrid_octet_kernel<<<blocks, THREADS>>>(x, emb, out);
    } else {
        int blocks = (n + PTS_PER_BLOCK - 1) / PTS_PER_BLOCK;
        hashgrid_gather_ilp4_kernel<<<blocks, THREADS>>>(
            x, (const float4*)emb, (float4*)out, n);
    }
}